// round 2
// baseline (speedup 1.0000x reference)
#include <cuda_runtime.h>
#include <cuda_bf16.h>
#include <cstdint>

// Problem shapes
#define B_IMG   64
#define H_IMG   256
#define W_IMG   256
#define PATCH   16
#define NPATCH  256            // (256/16)^2 per image
#define D_PATCH 256            // 16*16
#define ROWS    (B_IMG * NPATCH)   // 16384 patch rows
#define VROWS   4096
#define KDIM    256

#define N_PATCH_ELEMS (B_IMG * NPATCH * D_PATCH)   // 4194304
#define N_TOKENS      (B_IMG * NPATCH)             // 16384

// GEMM tiling
#define BM 128
#define BN 128
#define BK 32
#define TM 8
#define TN 8
#define SPAD 132               // padded row stride (floats) for 128-wide smem rows

// Shared memory layout (floats):
//   As   : [256][SPAD]  (K-major, m contiguous)    = 256*132 = 33792
//   Bs   : [2][BK][SPAD]                           = 2*32*132 = 8448
//   redS : [128][16]                               = 2048
//   redI : [128][16] (int)                         = 2048
#define AS_FLOATS   (KDIM * SPAD)
#define BS_FLOATS   (2 * BK * SPAD)
#define RED_FLOATS  (BM * 16)
#define SMEM_FLOATS (AS_FLOATS + BS_FLOATS + RED_FLOATS + RED_FLOATS)
#define SMEM_BYTES  (SMEM_FLOATS * 4)

// Scratch (device-global: no allocation allowed in kernel_launch)
__device__ float g_patches[N_PATCH_ELEMS];
__device__ float g_hv2[VROWS];

// ---------------------------------------------------------------------------
// Kernel 1: patchify. Raster patch order; each thread moves one float4
// (4 contiguous columns within one patch row == contiguous in image memory).
// ---------------------------------------------------------------------------
__global__ void patchify_kernel(const float* __restrict__ img,
                                float* __restrict__ out_opt) {
    int i = blockIdx.x * blockDim.x + threadIdx.x;     // float4 index
    if (i >= N_PATCH_ELEMS / 4) return;
    int f  = i << 2;
    int d  = f & 255;          // element within patch
    int pn = f >> 8;           // b*256 + n
    int b  = pn >> 8;
    int n  = pn & 255;
    int r  = d >> 4, c = d & 15;
    int py = n >> 4, px = n & 15;
    const float4 v = *(const float4*)(img + (size_t)b * (H_IMG * W_IMG)
                                      + (size_t)(py * PATCH + r) * W_IMG
                                      + px * PATCH + c);
    ((float4*)g_patches)[i] = v;
    if (out_opt) ((float4*)out_opt)[i] = v;
}

// ---------------------------------------------------------------------------
// Kernel 2: 0.5 * ||v||^2 per vocab row (one warp per row, shuffle reduce)
// ---------------------------------------------------------------------------
__global__ void vocab_norm_kernel(const float* __restrict__ vocab) {
    int gt   = blockIdx.x * blockDim.x + threadIdx.x;
    int w    = gt >> 5;
    int lane = gt & 31;
    if (w >= VROWS) return;
    const float4* row = (const float4*)(vocab + (size_t)w * KDIM);
    float s = 0.f;
    #pragma unroll
    for (int j = 0; j < 2; j++) {
        float4 q = row[lane + 32 * j];
        s += q.x * q.x + q.y * q.y + q.z * q.z + q.w * q.w;
    }
    #pragma unroll
    for (int off = 16; off; off >>= 1) s += __shfl_xor_sync(0xFFFFFFFFu, s, off);
    if (lane == 0) g_hv2[w] = 0.5f * s;
}

// ---------------------------------------------------------------------------
// Kernel 3: fused GEMM + row-argmax of (x.v - 0.5||v||^2).
// One block per 128 patch rows; loops over all 32 vocab tiles of 128.
// A tile (128 x 256) is SMEM-resident for the whole block; B is streamed in
// double-buffered K=32 chunks (LDG prefetch -> compute -> STS -> bar).
// ---------------------------------------------------------------------------
__global__ void __launch_bounds__(256, 1)
gemm_argmax_kernel(const float* __restrict__ vocab,
                   float* __restrict__ tok_f, int* __restrict__ tok_i) {
    extern __shared__ float sm[];
    float* As   = sm;
    float* Bs   = As + AS_FLOATS;
    float* redS = Bs + BS_FLOATS;
    int*   redI = (int*)(redS + RED_FLOATS);

    const int t  = threadIdx.x;
    const int m0 = blockIdx.x * BM;
    const int tx = t & 15;         // column group
    const int ty = t >> 4;         // row group
    const int mrow = ty * TM;
    const int ncol = tx * TN;

    // ---- Load A tile (128 rows x 256 K) once, transposed to K-major ----
    // 8192 float4 total -> 32 per thread.
    #pragma unroll
    for (int i = 0; i < 32; i++) {
        int f  = t + (i << 8);
        int m  = f >> 6;          // 64 float4 per row
        int k4 = f & 63;
        float4 q = *(const float4*)(g_patches + (size_t)(m0 + m) * KDIM + (k4 << 2));
        int k = k4 << 2;
        As[(k + 0) * SPAD + m] = q.x;
        As[(k + 1) * SPAD + m] = q.y;
        As[(k + 2) * SPAD + m] = q.z;
        As[(k + 3) * SPAD + m] = q.w;
    }
    __syncthreads();

    float best[TM];
    int   bidx[TM];
    #pragma unroll
    for (int i = 0; i < TM; i++) { best[i] = -3.4e38f; bidx[i] = 0; }

    for (int nt = 0; nt < VROWS / BN; nt++) {
        const int n0 = nt << 7;

        // ---- prologue: load + store chunk 0 of B ----
        float4 pre[4];
        #pragma unroll
        for (int i = 0; i < 4; i++) {
            int f  = t + (i << 8);     // 0..1023
            int n  = f >> 3;           // 8 float4 per vocab row per chunk
            int k4 = f & 7;
            pre[i] = *(const float4*)(vocab + (size_t)(n0 + n) * KDIM + (k4 << 2));
        }
        #pragma unroll
        for (int i = 0; i < 4; i++) {
            int f = t + (i << 8);
            int n = f >> 3, k = (f & 7) << 2;
            Bs[(k + 0) * SPAD + n] = pre[i].x;
            Bs[(k + 1) * SPAD + n] = pre[i].y;
            Bs[(k + 2) * SPAD + n] = pre[i].z;
            Bs[(k + 3) * SPAD + n] = pre[i].w;
        }
        __syncthreads();

        float acc[TM][TN];
        #pragma unroll
        for (int i = 0; i < TM; i++)
            #pragma unroll
            for (int j = 0; j < TN; j++) acc[i][j] = 0.f;

        for (int kc = 0; kc < KDIM / BK; kc++) {
            // prefetch next chunk into registers (overlaps with compute)
            if (kc < KDIM / BK - 1) {
                int kbase = (kc + 1) << 5;
                #pragma unroll
                for (int i = 0; i < 4; i++) {
                    int f  = t + (i << 8);
                    int n  = f >> 3;
                    int k4 = f & 7;
                    pre[i] = *(const float4*)(vocab + (size_t)(n0 + n) * KDIM
                                              + kbase + (k4 << 2));
                }
            }
            const float* Bc = Bs + (kc & 1) * (BK * SPAD);
            const int kglob = kc << 5;
            #pragma unroll
            for (int kk = 0; kk < BK; kk++) {
                const float* arow = As + (kglob + kk) * SPAD + mrow;
                const float* brow = Bc + kk * SPAD + ncol;
                float4 a0 = *(const float4*)(arow);
                float4 a1 = *(const float4*)(arow + 4);
                float4 b0 = *(const float4*)(brow);
                float4 b1 = *(const float4*)(brow + 4);
                float a[TM] = {a0.x, a0.y, a0.z, a0.w, a1.x, a1.y, a1.z, a1.w};
                float b[TN] = {b0.x, b0.y, b0.z, b0.w, b1.x, b1.y, b1.z, b1.w};
                #pragma unroll
                for (int i = 0; i < TM; i++)
                    #pragma unroll
                    for (int j = 0; j < TN; j++)
                        acc[i][j] = fmaf(a[i], b[j], acc[i][j]);
            }
            // store prefetched chunk into the other buffer
            if (kc < KDIM / BK - 1) {
                float* Bw = Bs + ((kc + 1) & 1) * (BK * SPAD);
                #pragma unroll
                for (int i = 0; i < 4; i++) {
                    int f = t + (i << 8);
                    int n = f >> 3, k = (f & 7) << 2;
                    Bw[(k + 0) * SPAD + n] = pre[i].x;
                    Bw[(k + 1) * SPAD + n] = pre[i].y;
                    Bw[(k + 2) * SPAD + n] = pre[i].z;
                    Bw[(k + 3) * SPAD + n] = pre[i].w;
                }
            }
            __syncthreads();
        }

        // ---- epilogue: score = x.v - 0.5||v||^2, running argmax ----
        #pragma unroll
        for (int j = 0; j < TN; j++) {
            int   vidx = n0 + ncol + j;
            float h    = g_hv2[vidx];
            #pragma unroll
            for (int i = 0; i < TM; i++) {
                float s = acc[i][j] - h;
                if (s > best[i]) { best[i] = s; bidx[i] = vidx; }
            }
        }
    }

    // ---- cross-thread reduction over the 16 column groups per row ----
    #pragma unroll
    for (int i = 0; i < TM; i++) {
        redS[(mrow + i) * 16 + tx] = best[i];
        redI[(mrow + i) * 16 + tx] = bidx[i];
    }
    __syncthreads();
    if (t < BM) {
        float bs = -3.4e38f;
        int   bi = 0x7FFFFFFF;
        #pragma unroll
        for (int j = 0; j < 16; j++) {
            float s  = redS[t * 16 + j];
            int   id = redI[t * 16 + j];
            if (s > bs || (s == bs && id < bi)) { bs = s; bi = id; }
        }
        int row = m0 + t;
        if (tok_f) tok_f[row] = (float)bi;
        if (tok_i) tok_i[row] = bi;
    }
}

// ---------------------------------------------------------------------------
extern "C" void kernel_launch(void* const* d_in, const int* in_sizes, int n_in,
                              void* d_out, int out_size) {
    const float* images = (const float*)d_in[0];   // [64,256,256] f32
    const float* vocab  = (const float*)d_in[1];   // [4096,256]  f32

    float* out       = (float*)d_out;
    float* patch_out = nullptr;
    float* tok_f     = nullptr;
    int*   tok_i     = nullptr;
    if (out_size >= N_PATCH_ELEMS + N_TOKENS) {
        patch_out = out;                 // patches, then tokens (as float)
        tok_f     = out + N_PATCH_ELEMS;
    } else if (out_size == N_PATCH_ELEMS) {
        patch_out = out;                 // patches only
    } else {
        tok_i = (int*)d_out;             // tokens only (int fallback)
    }

    cudaFuncSetAttribute(gemm_argmax_kernel,
                         cudaFuncAttributeMaxDynamicSharedMemorySize, SMEM_BYTES);

    // 1) patchify -> scratch (+ d_out patches region)
    {
        int nthr = N_PATCH_ELEMS / 4;
        patchify_kernel<<<(nthr + 255) / 256, 256>>>(images, patch_out);
    }
    // 2) 0.5*||v||^2
    {
        int nthr = VROWS * 32;
        vocab_norm_kernel<<<(nthr + 255) / 256, 256>>>(vocab);
    }
    // 3) fused GEMM + argmax -> tokens
    gemm_argmax_kernel<<<ROWS / BM, 256, SMEM_BYTES>>>(vocab, tok_f, tok_i);
}

// round 4
// speedup vs baseline: 1.2013x; 1.2013x over previous
#include <cuda_runtime.h>
#include <cuda_bf16.h>
#include <cstdint>

// ---------------- problem shapes ----------------
#define B_IMG   64
#define H_IMG   256
#define W_IMG   256
#define PATCH   16
#define ROWS    16384
#define VROWS   4096
#define KDIM    256
#define N_PATCH_ELEMS (ROWS * KDIM)
#define N_TOKENS      ROWS

// ---------------- tiling ----------------
#define M_CTA   128
#define N_TILE  128
#define NT_COUNT (VROWS / N_TILE)          // 32
#define KCHUNK  64
#define NKC     (KDIM / KCHUNK)            // 4
#define NCHUNKS (NT_COUNT * NKC)           // 128
#define TH_GAP  0.05f

// ---------------- SMEM layout (bytes) ----------------
// A hi: 4 panels x [128 rows x 64 bf16] SW128 = 65536  @ 0
// A lo: 65536                                          @ 65536
// B:    2 bufs x { hi 16384, lo 16384 } = 65536        @ 131072
// nhv2: 4096 f32 = 16384                               @ 196608
#define SM_A_HI 0
#define SM_A_LO 65536
#define SM_B    131072
#define SM_NHV  196608
#define SMEM_BYTES 212992
// reduction scratch reuses SM_B after mainloop: [4 wn][128 rows] float4 = 8KB

// ---------------- device scratch ----------------
__device__ float         g_patches[N_PATCH_ELEMS];
__device__ __nv_bfloat16 g_phi[N_PATCH_ELEMS];
__device__ __nv_bfloat16 g_plo[N_PATCH_ELEMS];
__device__ __nv_bfloat16 g_vhi[VROWS * KDIM];
__device__ __nv_bfloat16 g_vlo[VROWS * KDIM];
__device__ float         g_nhv2[VROWS];       // -0.5*||v||^2
__device__ int           g_fixcnt;
__device__ int           g_fixlist[ROWS];

// ---------------- helpers ----------------
__device__ __forceinline__ uint32_t smem_u32(const void* p) {
    uint32_t a;
    asm("{ .reg .u64 t; cvta.to.shared.u64 t, %1; cvt.u32.u64 %0, t; }" : "=r"(a) : "l"(p));
    return a;
}
#define SMEM_SWZ(off) ((uint32_t)(off) ^ (((uint32_t)(off) >> 3) & 0x70u))

__device__ __forceinline__ void ldm4(uint32_t* r, uint32_t addr) {
    asm volatile("ldmatrix.sync.aligned.m8n8.x4.shared.b16 {%0,%1,%2,%3}, [%4];"
        : "=r"(r[0]), "=r"(r[1]), "=r"(r[2]), "=r"(r[3]) : "r"(addr));
}
__device__ __forceinline__ void mma_bf16(float* c, const uint32_t* a, uint32_t b0, uint32_t b1) {
    asm volatile("mma.sync.aligned.m16n8k16.row.col.f32.bf16.bf16.f32 "
        "{%0,%1,%2,%3}, {%4,%5,%6,%7}, {%8,%9}, {%0,%1,%2,%3};"
        : "+f"(c[0]), "+f"(c[1]), "+f"(c[2]), "+f"(c[3])
        : "r"(a[0]), "r"(a[1]), "r"(a[2]), "r"(a[3]), "r"(b0), "r"(b1));
}
#define CP16(dst, src)  asm volatile("cp.async.cg.shared.global [%0], [%1], 16;" :: "r"(dst), "l"(src))
#define CP_COMMIT()     asm volatile("cp.async.commit_group;" ::: "memory")
#define CP_WAIT(n)      asm volatile("cp.async.wait_group %0;" :: "n"(n) : "memory")

__device__ __forceinline__ uint32_t pack2bf(__nv_bfloat16 a, __nv_bfloat16 b) {
    return (uint32_t)__bfloat16_as_ushort(a) | ((uint32_t)__bfloat16_as_ushort(b) << 16);
}

// ---------------------------------------------------------------------------
// Kernel 1: patchify + bf16 hi/lo split
// ---------------------------------------------------------------------------
__global__ void patchify_split_kernel(const float* __restrict__ img,
                                      float* __restrict__ out_opt) {
    int i = blockIdx.x * blockDim.x + threadIdx.x;
    if (blockIdx.x == 0 && threadIdx.x == 0) g_fixcnt = 0;
    if (i >= N_PATCH_ELEMS / 4) return;
    int f  = i << 2;
    int d  = f & 255;
    int pn = f >> 8;
    int b  = pn >> 8;
    int n  = pn & 255;
    int r  = d >> 4, c = d & 15;
    int py = n >> 4, px = n & 15;
    const float4 v = *(const float4*)(img + (size_t)b * (H_IMG * W_IMG)
                                      + (size_t)(py * PATCH + r) * W_IMG + px * PATCH + c);
    ((float4*)g_patches)[i] = v;
    if (out_opt) ((float4*)out_opt)[i] = v;

    float x[4] = {v.x, v.y, v.z, v.w};
    __nv_bfloat16 hi[4], lo[4];
    #pragma unroll
    for (int j = 0; j < 4; j++) {
        hi[j] = __float2bfloat16_rn(x[j]);
        lo[j] = __float2bfloat16_rn(x[j] - __bfloat162float(hi[j]));
    }
    uint2 ph, pl;
    ph.x = pack2bf(hi[0], hi[1]); ph.y = pack2bf(hi[2], hi[3]);
    pl.x = pack2bf(lo[0], lo[1]); pl.y = pack2bf(lo[2], lo[3]);
    ((uint2*)g_phi)[i] = ph;
    ((uint2*)g_plo)[i] = pl;
}

// ---------------------------------------------------------------------------
// Kernel 2: vocab prep — -0.5||v||^2 + bf16 hi/lo split (1 warp / row)
// ---------------------------------------------------------------------------
__global__ void vocab_prep_kernel(const float* __restrict__ vocab) {
    int gt   = blockIdx.x * blockDim.x + threadIdx.x;
    int w    = gt >> 5;
    int lane = gt & 31;
    if (w >= VROWS) return;
    float s = 0.f;
    #pragma unroll
    for (int j = 0; j < 2; j++) {
        int e = lane * 4 + j * 128;
        float4 q = *(const float4*)(vocab + (size_t)w * KDIM + e);
        s += q.x * q.x + q.y * q.y + q.z * q.z + q.w * q.w;
        float x[4] = {q.x, q.y, q.z, q.w};
        __nv_bfloat16 hi[4], lo[4];
        #pragma unroll
        for (int t = 0; t < 4; t++) {
            hi[t] = __float2bfloat16_rn(x[t]);
            lo[t] = __float2bfloat16_rn(x[t] - __bfloat162float(hi[t]));
        }
        uint2 ph, pl;
        ph.x = pack2bf(hi[0], hi[1]); ph.y = pack2bf(hi[2], hi[3]);
        pl.x = pack2bf(lo[0], lo[1]); pl.y = pack2bf(lo[2], lo[3]);
        *(uint2*)(g_vhi + (size_t)w * KDIM + e) = ph;
        *(uint2*)(g_vlo + (size_t)w * KDIM + e) = pl;
    }
    #pragma unroll
    for (int off = 16; off; off >>= 1) s += __shfl_xor_sync(0xFFFFFFFFu, s, off);
    if (lane == 0) g_nhv2[w] = -0.5f * s;
}

// ---------------------------------------------------------------------------
// Kernel 3: mma.sync bf16 3-term GEMM + fused top-2 argmax
//   8 warps: 2(M) x 4(N) grid, warp tile 64x32. A SMEM-resident, B cp.async
//   double-buffered in K=64 chunks.
// ---------------------------------------------------------------------------
__global__ void __launch_bounds__(256, 1)
gemm_mma_kernel(float* __restrict__ tok_f, int* __restrict__ tok_i) {
    extern __shared__ char smem[];
    const uint32_t sb = smem_u32(smem);
    const int t    = threadIdx.x;
    const int wid  = t >> 5;
    const int lane = t & 31;
    const int wm   = wid >> 2;          // 0..1
    const int wn   = wid & 3;           // 0..3
    const int grp  = lane >> 2;         // 0..7
    const int tig  = lane & 3;          // 0..3
    const int m0   = blockIdx.x * M_CTA;

    // preload -0.5||v||^2
    for (int i = t; i < VROWS / 4; i += 256)
        ((float4*)(smem + SM_NHV))[i] = ((const float4*)g_nhv2)[i];

    // A panels (hi+lo), SW128 swizzled, K-panel-major
    #pragma unroll
    for (int i = 0; i < 16; i++) {
        int f = t + (i << 8);            // 0..4095
        int m = f >> 5;                  // 0..127
        int c = f & 31;                  // 16B chunk in 512B row
        int panel = c >> 3;
        int q = c & 7;
        uint32_t dst = SMEM_SWZ(m * 128 + q * 16);
        *(uint4*)(smem + SM_A_HI + panel * 16384 + dst) =
            *(const uint4*)(g_phi + (size_t)(m0 + m) * KDIM + c * 8);
        *(uint4*)(smem + SM_A_LO + panel * 16384 + dst) =
            *(const uint4*)(g_plo + (size_t)(m0 + m) * KDIM + c * 8);
    }
    __syncthreads();

    // prologue: chunk 0
    {
        const int n0 = 0, kc = 0;
        #pragma unroll
        for (int i = 0; i < 8; i++) {
            int f = t + (i << 8);
            int half = f >> 10, rem = f & 1023, r = rem >> 3, q = rem & 7;
            uint32_t dst = sb + SM_B + half * 16384 + SMEM_SWZ(r * 128 + q * 16);
            const __nv_bfloat16* src = (half ? g_vlo : g_vhi)
                + (size_t)(n0 + r) * KDIM + kc * 64 + q * 8;
            CP16(dst, src);
        }
        CP_COMMIT();
    }

    float acc[4][4][4];
    #pragma unroll
    for (int a = 0; a < 4; a++)
        #pragma unroll
        for (int b = 0; b < 4; b++)
            #pragma unroll
            for (int c = 0; c < 4; c++) acc[a][b][c] = 0.f;

    float b1v[8], b2v[8];
    int   i1v[8];
    #pragma unroll
    for (int r = 0; r < 8; r++) { b1v[r] = -3.4e38f; b2v[r] = -3.4e38f; i1v[r] = 0; }

    const float* nhv = (const float*)(smem + SM_NHV);

    for (int gch = 0; gch < NCHUNKS; gch++) {
        const int nt  = gch >> 2;
        const int kc  = gch & 3;
        const int buf = gch & 1;

        if (gch < NCHUNKS - 1) {
            const int gn  = gch + 1;
            const int nn0 = (gn >> 2) << 7;
            const int nkc = gn & 3;
            const uint32_t bb = sb + SM_B + (gn & 1) * 32768;
            #pragma unroll
            for (int i = 0; i < 8; i++) {
                int f = t + (i << 8);
                int half = f >> 10, rem = f & 1023, r = rem >> 3, q = rem & 7;
                uint32_t dst = bb + half * 16384 + SMEM_SWZ(r * 128 + q * 16);
                const __nv_bfloat16* src = (half ? g_vlo : g_vhi)
                    + (size_t)(nn0 + r) * KDIM + nkc * 64 + q * 8;
                CP16(dst, src);
            }
            CP_COMMIT();
            CP_WAIT(1);
        } else {
            CP_WAIT(0);
        }
        __syncthreads();

        const uint32_t bh_base = sb + SM_B + buf * 32768;
        const uint32_t bl_base = bh_base + 16384;
        const uint32_t ah_base = sb + SM_A_HI + kc * 16384;
        const uint32_t al_base = sb + SM_A_LO + kc * 16384;
        const int rowA = wm * 64 + (lane & 15);
        const int rowB = wn * 32 + (lane & 15);

        #pragma unroll
        for (int ks = 0; ks < 4; ks++) {
            const uint32_t colb = ks * 32 + (lane >> 4) * 16;
            uint32_t ah[4][4], al[4][4], bh[2][4], bl[2][4];
            #pragma unroll
            for (int mt = 0; mt < 4; mt++) {
                ldm4(ah[mt], ah_base + SMEM_SWZ((rowA + mt * 16) * 128 + colb));
                ldm4(al[mt], al_base + SMEM_SWZ((rowA + mt * 16) * 128 + colb));
            }
            #pragma unroll
            for (int p = 0; p < 2; p++) {
                ldm4(bh[p], bh_base + SMEM_SWZ((rowB + p * 16) * 128 + colb));
                ldm4(bl[p], bl_base + SMEM_SWZ((rowB + p * 16) * 128 + colb));
            }
            #pragma unroll
            for (int mt = 0; mt < 4; mt++) {
                #pragma unroll
                for (int n8 = 0; n8 < 4; n8++) {
                    const int p = n8 >> 1, w = n8 & 1;
                    const uint32_t h0 = w ? bh[p][1] : bh[p][0];
                    const uint32_t h1 = w ? bh[p][3] : bh[p][2];
                    const uint32_t l0 = w ? bl[p][1] : bl[p][0];
                    const uint32_t l1 = w ? bl[p][3] : bl[p][2];
                    mma_bf16(acc[mt][n8], ah[mt], h0, h1);
                    mma_bf16(acc[mt][n8], ah[mt], l0, l1);
                    mma_bf16(acc[mt][n8], al[mt], h0, h1);
                }
            }
        }
        __syncthreads();

        if (kc == 3) {
            // epilogue: scores + running top-2
            #pragma unroll
            for (int mt = 0; mt < 4; mt++) {
                #pragma unroll
                for (int n8 = 0; n8 < 4; n8++) {
                    const int cb = nt * 128 + wn * 32 + n8 * 8 + tig * 2;
                    const float2 h = *(const float2*)(nhv + cb);
                    const float s00 = acc[mt][n8][0] + h.x;
                    const float s01 = acc[mt][n8][1] + h.y;
                    const float s10 = acc[mt][n8][2] + h.x;
                    const float s11 = acc[mt][n8][3] + h.y;
                    const int r0 = mt * 2, r1 = mt * 2 + 1;
                    if (s00 > b1v[r0]) { b2v[r0] = b1v[r0]; b1v[r0] = s00; i1v[r0] = cb; }
                    else if (s00 > b2v[r0]) b2v[r0] = s00;
                    if (s01 > b1v[r0]) { b2v[r0] = b1v[r0]; b1v[r0] = s01; i1v[r0] = cb + 1; }
                    else if (s01 > b2v[r0]) b2v[r0] = s01;
                    if (s10 > b1v[r1]) { b2v[r1] = b1v[r1]; b1v[r1] = s10; i1v[r1] = cb; }
                    else if (s10 > b2v[r1]) b2v[r1] = s10;
                    if (s11 > b1v[r1]) { b2v[r1] = b1v[r1]; b1v[r1] = s11; i1v[r1] = cb + 1; }
                    else if (s11 > b2v[r1]) b2v[r1] = s11;
                    acc[mt][n8][0] = 0.f; acc[mt][n8][1] = 0.f;
                    acc[mt][n8][2] = 0.f; acc[mt][n8][3] = 0.f;
                }
            }
        }
    }

    // ---- cross-lane merge (lanes sharing same rows: xor over lane bits 0,1) ----
    #pragma unroll
    for (int d = 1; d <= 2; d <<= 1) {
        #pragma unroll
        for (int r = 0; r < 8; r++) {
            float ob1 = __shfl_xor_sync(0xFFFFFFFFu, b1v[r], d);
            float ob2 = __shfl_xor_sync(0xFFFFFFFFu, b2v[r], d);
            int   oi1 = __shfl_xor_sync(0xFFFFFFFFu, i1v[r], d);
            if (ob1 > b1v[r] || (ob1 == b1v[r] && oi1 < i1v[r])) {
                b2v[r] = fmaxf(b1v[r], ob2);
                b1v[r] = ob1; i1v[r] = oi1;
            } else {
                b2v[r] = fmaxf(b2v[r], ob1);
            }
        }
    }

    // ---- cross-warp reduction via SMEM (reuse B area) ----
    __syncthreads();
    float4* red = (float4*)(smem + SM_B);    // [4 wn][128 rows]
    if (tig == 0) {
        #pragma unroll
        for (int mt = 0; mt < 4; mt++) {
            #pragma unroll
            for (int h = 0; h < 2; h++) {
                const int rl = wm * 64 + mt * 16 + grp + h * 8;
                const int r  = mt * 2 + h;
                red[wn * 128 + rl] = make_float4(b1v[r], b2v[r], __int_as_float(i1v[r]), 0.f);
            }
        }
    }
    __syncthreads();
    if (t < M_CTA) {
        float bb1 = -3.4e38f, bb2 = -3.4e38f;
        int   bi  = 0x7FFFFFFF;
        #pragma unroll
        for (int w = 0; w < 4; w++) {
            float4 e = red[w * 128 + t];
            float ob1 = e.x, ob2 = e.y;
            int   oi1 = __float_as_int(e.z);
            if (ob1 > bb1 || (ob1 == bb1 && oi1 < bi)) {
                bb2 = fmaxf(bb1, ob2); bb1 = ob1; bi = oi1;
            } else {
                bb2 = fmaxf(bb2, ob1);
            }
        }
        const int row = m0 + t;
        if (tok_f) tok_f[row] = (float)bi;
        if (tok_i) tok_i[row] = bi;
        if (bb1 - bb2 < TH_GAP) {
            int pos = atomicAdd(&g_fixcnt, 1);
            g_fixlist[pos] = row;
        }
    }
}

// ---------------------------------------------------------------------------
// Kernel 4: exact fp32 rescore for flagged rows (list-compacted)
// ---------------------------------------------------------------------------
__global__ void __launch_bounds__(128)
fixup_kernel(const float* __restrict__ vocab,
             float* __restrict__ tok_f, int* __restrict__ tok_i) {
    __shared__ float xs[KDIM];
    __shared__ float rb[128];
    __shared__ int   ri[128];
    const int t = threadIdx.x;
    const int cnt = g_fixcnt;
    for (int li = blockIdx.x; li < cnt; li += gridDim.x) {
        const int row = g_fixlist[li];
        xs[t]       = g_patches[(size_t)row * KDIM + t];
        xs[t + 128] = g_patches[(size_t)row * KDIM + t + 128];
        __syncthreads();

        float best = -3.4e38f;
        int   bi   = 0;
        for (int v = t; v < VROWS; v += 128) {
            const float4* vr = (const float4*)(vocab + (size_t)v * KDIM);
            float s = 0.f;
            #pragma unroll
            for (int k = 0; k < KDIM / 4; k++) {
                float4 q = vr[k];
                s = fmaf(xs[k * 4 + 0], q.x, s);
                s = fmaf(xs[k * 4 + 1], q.y, s);
                s = fmaf(xs[k * 4 + 2], q.z, s);
                s = fmaf(xs[k * 4 + 3], q.w, s);
            }
            s += g_nhv2[v];
            if (s > best) { best = s; bi = v; }
        }
        rb[t] = best; ri[t] = bi;
        __syncthreads();
        if (t == 0) {
            float bs = -3.4e38f;
            int   bj = 0x7FFFFFFF;
            for (int j = 0; j < 128; j++) {
                float s = rb[j]; int id = ri[j];
                if (s > bs || (s == bs && id < bj)) { bs = s; bj = id; }
            }
            if (tok_f) tok_f[row] = (float)bj;
            if (tok_i) tok_i[row] = bj;
        }
        __syncthreads();
    }
}

// ---------------------------------------------------------------------------
extern "C" void kernel_launch(void* const* d_in, const int* in_sizes, int n_in,
                              void* d_out, int out_size) {
    const float* images = (const float*)d_in[0];
    const float* vocab  = (const float*)d_in[1];

    float* out       = (float*)d_out;
    float* patch_out = nullptr;
    float* tok_f     = nullptr;
    int*   tok_i     = nullptr;
    if (out_size >= N_PATCH_ELEMS + N_TOKENS) {
        patch_out = out;
        tok_f     = out + N_PATCH_ELEMS;
    } else if (out_size == N_PATCH_ELEMS) {
        patch_out = out;
    } else {
        tok_i = (int*)d_out;
    }

    cudaFuncSetAttribute(gemm_mma_kernel,
                         cudaFuncAttributeMaxDynamicSharedMemorySize, SMEM_BYTES);

    patchify_split_kernel<<<(N_PATCH_ELEMS / 4 + 255) / 256, 256>>>(images, patch_out);
    vocab_prep_kernel<<<(VROWS * 32 + 255) / 256, 256>>>(vocab);
    gemm_mma_kernel<<<ROWS / M_CTA, 256, SMEM_BYTES>>>(tok_f, tok_i);
    fixup_kernel<<<256, 128>>>(vocab, tok_f, tok_i);
}

// round 5
// speedup vs baseline: 1.9878x; 1.6546x over previous
#include <cuda_runtime.h>
#include <cuda_fp16.h>
#include <cstdint>

// ---------------- problem shapes ----------------
#define B_IMG   64
#define H_IMG   256
#define W_IMG   256
#define PATCH   16
#define ROWS    16384
#define VROWS   4096
#define KDIM    256
#define N_PATCH_ELEMS (ROWS * KDIM)
#define N_TOKENS      ROWS

// ---------------- tiling ----------------
#define M_CTA   128
#define N_TILE  128
#define NT_COUNT (VROWS / N_TILE)          // 32
#define KCHUNK  64
#define NKC     (KDIM / KCHUNK)            // 4
#define NCHUNKS (NT_COUNT * NKC)           // 128
#define TH_GAP  0.05f
#define FIX_RPB 8

// ---------------- SMEM layout (bytes) ----------------
// A: 4 panels x [128 rows x 64 fp16] SW128 = 65536   @ 0
// B: 2 bufs x 16384 = 32768                          @ 65536
// nhv2: 4096 f32 = 16384                             @ 98304
#define SM_A    0
#define SM_B    65536
#define SM_NHV  98304
#define SMEM_BYTES 114688
// cross-warp reduction scratch reuses SM_B after mainloop (8KB needed)

// ---------------- device scratch ----------------
__device__ float  g_patches[N_PATCH_ELEMS];
__device__ __half g_ph[N_PATCH_ELEMS];
__device__ __half g_vh[VROWS * KDIM];
__device__ float  g_nhv2[VROWS];            // -0.5*||v||^2
__device__ int    g_fixcnt;
__device__ int    g_fixlist[ROWS];

// ---------------- helpers ----------------
__device__ __forceinline__ uint32_t smem_u32(const void* p) {
    uint32_t a;
    asm("{ .reg .u64 t; cvta.to.shared.u64 t, %1; cvt.u32.u64 %0, t; }" : "=r"(a) : "l"(p));
    return a;
}
#define SMEM_SWZ(off) ((uint32_t)(off) ^ (((uint32_t)(off) >> 3) & 0x70u))

__device__ __forceinline__ void ldm4(uint32_t* r, uint32_t addr) {
    asm volatile("ldmatrix.sync.aligned.m8n8.x4.shared.b16 {%0,%1,%2,%3}, [%4];"
        : "=r"(r[0]), "=r"(r[1]), "=r"(r[2]), "=r"(r[3]) : "r"(addr));
}
__device__ __forceinline__ void mma_f16(float* c, const uint32_t* a, uint32_t b0, uint32_t b1) {
    asm volatile("mma.sync.aligned.m16n8k16.row.col.f32.f16.f16.f32 "
        "{%0,%1,%2,%3}, {%4,%5,%6,%7}, {%8,%9}, {%0,%1,%2,%3};"
        : "+f"(c[0]), "+f"(c[1]), "+f"(c[2]), "+f"(c[3])
        : "r"(a[0]), "r"(a[1]), "r"(a[2]), "r"(a[3]), "r"(b0), "r"(b1));
}
#define CP16(dst, src)  asm volatile("cp.async.cg.shared.global [%0], [%1], 16;" :: "r"(dst), "l"(src))
#define CP_COMMIT()     asm volatile("cp.async.commit_group;" ::: "memory")
#define CP_WAIT(n)      asm volatile("cp.async.wait_group %0;" :: "n"(n) : "memory")

__device__ __forceinline__ uint32_t pack2h(__half a, __half b) {
    return (uint32_t)__half_as_ushort(a) | ((uint32_t)__half_as_ushort(b) << 16);
}

// ---------------------------------------------------------------------------
// Kernel 1: patchify + fp16 copy
// ---------------------------------------------------------------------------
__global__ void patchify_kernel(const float* __restrict__ img,
                                float* __restrict__ out_opt) {
    int i = blockIdx.x * blockDim.x + threadIdx.x;
    if (blockIdx.x == 0 && threadIdx.x == 0) g_fixcnt = 0;
    if (i >= N_PATCH_ELEMS / 4) return;
    int f  = i << 2;
    int d  = f & 255;
    int pn = f >> 8;
    int b  = pn >> 8;
    int n  = pn & 255;
    int r  = d >> 4, c = d & 15;
    int py = n >> 4, px = n & 15;
    const float4 v = *(const float4*)(img + (size_t)b * (H_IMG * W_IMG)
                                      + (size_t)(py * PATCH + r) * W_IMG + px * PATCH + c);
    ((float4*)g_patches)[i] = v;
    if (out_opt) ((float4*)out_opt)[i] = v;
    uint2 ph;
    ph.x = pack2h(__float2half_rn(v.x), __float2half_rn(v.y));
    ph.y = pack2h(__float2half_rn(v.z), __float2half_rn(v.w));
    ((uint2*)g_ph)[i] = ph;
}

// ---------------------------------------------------------------------------
// Kernel 2: vocab prep — -0.5||v||^2 + fp16 copy (1 warp / row)
// ---------------------------------------------------------------------------
__global__ void vocab_prep_kernel(const float* __restrict__ vocab) {
    int gt   = blockIdx.x * blockDim.x + threadIdx.x;
    int w    = gt >> 5;
    int lane = gt & 31;
    if (w >= VROWS) return;
    float s = 0.f;
    #pragma unroll
    for (int j = 0; j < 2; j++) {
        int e = lane * 4 + j * 128;
        float4 q = *(const float4*)(vocab + (size_t)w * KDIM + e);
        s += q.x * q.x + q.y * q.y + q.z * q.z + q.w * q.w;
        uint2 ph;
        ph.x = pack2h(__float2half_rn(q.x), __float2half_rn(q.y));
        ph.y = pack2h(__float2half_rn(q.z), __float2half_rn(q.w));
        *(uint2*)(g_vh + (size_t)w * KDIM + e) = ph;
    }
    #pragma unroll
    for (int off = 16; off; off >>= 1) s += __shfl_xor_sync(0xFFFFFFFFu, s, off);
    if (lane == 0) g_nhv2[w] = -0.5f * s;
}

// ---------------------------------------------------------------------------
// Kernel 3: single-term fp16 mma.sync GEMM + fused top-2 argmax
// ---------------------------------------------------------------------------
__global__ void __launch_bounds__(256, 1)
gemm_mma_kernel(float* __restrict__ tok_f, int* __restrict__ tok_i) {
    extern __shared__ char smem[];
    const uint32_t sb = smem_u32(smem);
    const int t    = threadIdx.x;
    const int wid  = t >> 5;
    const int lane = t & 31;
    const int wm   = wid >> 2;          // 0..1
    const int wn   = wid & 3;           // 0..3
    const int grp  = lane >> 2;         // 0..7
    const int tig  = lane & 3;          // 0..3
    const int m0   = blockIdx.x * M_CTA;

    for (int i = t; i < VROWS / 4; i += 256)
        ((float4*)(smem + SM_NHV))[i] = ((const float4*)g_nhv2)[i];

    // A panels, SW128 swizzled, K-panel-major
    #pragma unroll
    for (int i = 0; i < 16; i++) {
        int f = t + (i << 8);            // 0..4095 16B chunks
        int m = f >> 5;                  // 0..127
        int c = f & 31;                  // chunk in 512B row
        int panel = c >> 3;
        int q = c & 7;
        uint32_t dst = SMEM_SWZ(m * 128 + q * 16);
        *(uint4*)(smem + SM_A + panel * 16384 + dst) =
            *(const uint4*)(g_ph + (size_t)(m0 + m) * KDIM + c * 8);
    }
    __syncthreads();

    // prologue: chunk 0
    #pragma unroll
    for (int i = 0; i < 4; i++) {
        int f = t + (i << 8);            // 0..1023
        int r = f >> 3, q = f & 7;
        uint32_t dst = sb + SM_B + SMEM_SWZ(r * 128 + q * 16);
        CP16(dst, g_vh + (size_t)r * KDIM + q * 8);
    }
    CP_COMMIT();

    float acc[4][4][4];
    #pragma unroll
    for (int a = 0; a < 4; a++)
        #pragma unroll
        for (int b = 0; b < 4; b++)
            #pragma unroll
            for (int c = 0; c < 4; c++) acc[a][b][c] = 0.f;

    float b1v[8], b2v[8];
    int   i1v[8];
    #pragma unroll
    for (int r = 0; r < 8; r++) { b1v[r] = -3.4e38f; b2v[r] = -3.4e38f; i1v[r] = 0; }

    const float* nhv = (const float*)(smem + SM_NHV);

    for (int gch = 0; gch < NCHUNKS; gch++) {
        const int nt  = gch >> 2;
        const int kc  = gch & 3;
        const int buf = gch & 1;

        if (gch < NCHUNKS - 1) {
            const int gn  = gch + 1;
            const int nn0 = (gn >> 2) << 7;
            const int nkc = gn & 3;
            const uint32_t bb = sb + SM_B + (gn & 1) * 16384;
            #pragma unroll
            for (int i = 0; i < 4; i++) {
                int f = t + (i << 8);
                int r = f >> 3, q = f & 7;
                uint32_t dst = bb + SMEM_SWZ(r * 128 + q * 16);
                CP16(dst, g_vh + (size_t)(nn0 + r) * KDIM + nkc * 64 + q * 8);
            }
            CP_COMMIT();
            CP_WAIT(1);
        } else {
            CP_WAIT(0);
        }
        __syncthreads();

        const uint32_t b_base = sb + SM_B + buf * 16384;
        const uint32_t a_base = sb + SM_A + kc * 16384;
        const int rowA = wm * 64 + (lane & 15);
        const int rowB = wn * 32 + (lane & 15);

        #pragma unroll
        for (int ks = 0; ks < 4; ks++) {
            const uint32_t colb = ks * 32 + (lane >> 4) * 16;
            uint32_t ah[4][4], bh[2][4];
            #pragma unroll
            for (int mt = 0; mt < 4; mt++)
                ldm4(ah[mt], a_base + SMEM_SWZ((rowA + mt * 16) * 128 + colb));
            #pragma unroll
            for (int p = 0; p < 2; p++)
                ldm4(bh[p], b_base + SMEM_SWZ((rowB + p * 16) * 128 + colb));
            #pragma unroll
            for (int mt = 0; mt < 4; mt++) {
                #pragma unroll
                for (int n8 = 0; n8 < 4; n8++) {
                    const int p = n8 >> 1, w = n8 & 1;
                    mma_f16(acc[mt][n8], ah[mt],
                            w ? bh[p][1] : bh[p][0],
                            w ? bh[p][3] : bh[p][2]);
                }
            }
        }
        __syncthreads();

        if (kc == 3) {
            #pragma unroll
            for (int mt = 0; mt < 4; mt++) {
                #pragma unroll
                for (int n8 = 0; n8 < 4; n8++) {
                    const int cb = nt * 128 + wn * 32 + n8 * 8 + tig * 2;
                    const float2 h = *(const float2*)(nhv + cb);
                    const float s00 = acc[mt][n8][0] + h.x;
                    const float s01 = acc[mt][n8][1] + h.y;
                    const float s10 = acc[mt][n8][2] + h.x;
                    const float s11 = acc[mt][n8][3] + h.y;
                    const int r0 = mt * 2, r1 = mt * 2 + 1;
                    if (s00 > b1v[r0]) { b2v[r0] = b1v[r0]; b1v[r0] = s00; i1v[r0] = cb; }
                    else if (s00 > b2v[r0]) b2v[r0] = s00;
                    if (s01 > b1v[r0]) { b2v[r0] = b1v[r0]; b1v[r0] = s01; i1v[r0] = cb + 1; }
                    else if (s01 > b2v[r0]) b2v[r0] = s01;
                    if (s10 > b1v[r1]) { b2v[r1] = b1v[r1]; b1v[r1] = s10; i1v[r1] = cb; }
                    else if (s10 > b2v[r1]) b2v[r1] = s10;
                    if (s11 > b1v[r1]) { b2v[r1] = b1v[r1]; b1v[r1] = s11; i1v[r1] = cb + 1; }
                    else if (s11 > b2v[r1]) b2v[r1] = s11;
                    acc[mt][n8][0] = 0.f; acc[mt][n8][1] = 0.f;
                    acc[mt][n8][2] = 0.f; acc[mt][n8][3] = 0.f;
                }
            }
        }
    }

    // cross-lane merge (xor lane bits 0,1 — lanes covering same rows)
    #pragma unroll
    for (int d = 1; d <= 2; d <<= 1) {
        #pragma unroll
        for (int r = 0; r < 8; r++) {
            float ob1 = __shfl_xor_sync(0xFFFFFFFFu, b1v[r], d);
            float ob2 = __shfl_xor_sync(0xFFFFFFFFu, b2v[r], d);
            int   oi1 = __shfl_xor_sync(0xFFFFFFFFu, i1v[r], d);
            if (ob1 > b1v[r] || (ob1 == b1v[r] && oi1 < i1v[r])) {
                b2v[r] = fmaxf(b1v[r], ob2);
                b1v[r] = ob1; i1v[r] = oi1;
            } else {
                b2v[r] = fmaxf(b2v[r], ob1);
            }
        }
    }

    // cross-warp reduction via SMEM (reuse B area)
    __syncthreads();
    float4* red = (float4*)(smem + SM_B);    // [4 wn][128 rows]
    if (tig == 0) {
        #pragma unroll
        for (int mt = 0; mt < 4; mt++) {
            #pragma unroll
            for (int h = 0; h < 2; h++) {
                const int rl = wm * 64 + mt * 16 + grp + h * 8;
                const int r  = mt * 2 + h;
                red[wn * 128 + rl] = make_float4(b1v[r], b2v[r], __int_as_float(i1v[r]), 0.f);
            }
        }
    }
    __syncthreads();
    if (t < M_CTA) {
        float bb1 = -3.4e38f, bb2 = -3.4e38f;
        int   bi  = 0x7FFFFFFF;
        #pragma unroll
        for (int w = 0; w < 4; w++) {
            float4 e = red[w * 128 + t];
            float ob1 = e.x, ob2 = e.y;
            int   oi1 = __float_as_int(e.z);
            if (ob1 > bb1 || (ob1 == bb1 && oi1 < bi)) {
                bb2 = fmaxf(bb1, ob2); bb1 = ob1; bi = oi1;
            } else {
                bb2 = fmaxf(bb2, ob1);
            }
        }
        const int row = m0 + t;
        if (tok_f) tok_f[row] = (float)bi;
        if (tok_i) tok_i[row] = bi;
        if (bb1 - bb2 < TH_GAP) {
            int pos = atomicAdd(&g_fixcnt, 1);
            g_fixlist[pos] = row;
        }
    }
}

// ---------------------------------------------------------------------------
// Kernel 4: exact fp32 rescore, 8 flagged rows per block (vocab read shared)
// ---------------------------------------------------------------------------
__global__ void __launch_bounds__(256)
fixup_kernel(const float* __restrict__ vocab,
             float* __restrict__ tok_f, int* __restrict__ tok_i) {
    __shared__ float xs[FIX_RPB][KDIM];
    __shared__ float rbv[FIX_RPB][256];
    __shared__ int   rbi[FIX_RPB][256];
    const int t   = threadIdx.x;
    const int cnt = g_fixcnt;
    for (int base = blockIdx.x * FIX_RPB; base < cnt; base += gridDim.x * FIX_RPB) {
        const int nr = min(FIX_RPB, cnt - base);
        __syncthreads();
        for (int i = t; i < nr * KDIM; i += 256) {
            int r = i >> 8, k = i & 255;
            xs[r][k] = g_patches[(size_t)g_fixlist[base + r] * KDIM + k];
        }
        __syncthreads();

        float best[FIX_RPB];
        int   bidx[FIX_RPB];
        #pragma unroll
        for (int r = 0; r < FIX_RPB; r++) { best[r] = -3.4e38f; bidx[r] = 0; }

        for (int v = t; v < VROWS; v += 256) {
            const float4* vr = (const float4*)(vocab + (size_t)v * KDIM);
            float acc[FIX_RPB];
            #pragma unroll
            for (int r = 0; r < FIX_RPB; r++) acc[r] = 0.f;
            #pragma unroll 4
            for (int k = 0; k < KDIM / 4; k++) {
                float4 q = vr[k];
                #pragma unroll
                for (int r = 0; r < FIX_RPB; r++) {
                    acc[r] = fmaf(xs[r][4 * k + 0], q.x, acc[r]);
                    acc[r] = fmaf(xs[r][4 * k + 1], q.y, acc[r]);
                    acc[r] = fmaf(xs[r][4 * k + 2], q.z, acc[r]);
                    acc[r] = fmaf(xs[r][4 * k + 3], q.w, acc[r]);
                }
            }
            const float h = g_nhv2[v];
            #pragma unroll
            for (int r = 0; r < FIX_RPB; r++) {
                float s = acc[r] + h;
                if (s > best[r]) { best[r] = s; bidx[r] = v; }
            }
        }
        #pragma unroll
        for (int r = 0; r < FIX_RPB; r++) { rbv[r][t] = best[r]; rbi[r][t] = bidx[r]; }
        __syncthreads();

        const int w = t >> 5, lane = t & 31;
        if (w < nr) {
            float bs = -3.4e38f;
            int   bj = 0x7FFFFFFF;
            #pragma unroll
            for (int j = 0; j < 8; j++) {
                float s  = rbv[w][lane + 32 * j];
                int   id = rbi[w][lane + 32 * j];
                if (s > bs || (s == bs && id < bj)) { bs = s; bj = id; }
            }
            #pragma unroll
            for (int off = 16; off; off >>= 1) {
                float os  = __shfl_xor_sync(0xFFFFFFFFu, bs, off);
                int   oid = __shfl_xor_sync(0xFFFFFFFFu, bj, off);
                if (os > bs || (os == bs && oid < bj)) { bs = os; bj = oid; }
            }
            if (lane == 0) {
                const int row = g_fixlist[base + w];
                if (tok_f) tok_f[row] = (float)bj;
                if (tok_i) tok_i[row] = bj;
            }
        }
    }
}

// ---------------------------------------------------------------------------
extern "C" void kernel_launch(void* const* d_in, const int* in_sizes, int n_in,
                              void* d_out, int out_size) {
    const float* images = (const float*)d_in[0];
    const float* vocab  = (const float*)d_in[1];

    float* out       = (float*)d_out;
    float* patch_out = nullptr;
    float* tok_f     = nullptr;
    int*   tok_i     = nullptr;
    if (out_size >= N_PATCH_ELEMS + N_TOKENS) {
        patch_out = out;
        tok_f     = out + N_PATCH_ELEMS;
    } else if (out_size == N_PATCH_ELEMS) {
        patch_out = out;
    } else {
        tok_i = (int*)d_out;
    }

    cudaFuncSetAttribute(gemm_mma_kernel,
                         cudaFuncAttributeMaxDynamicSharedMemorySize, SMEM_BYTES);

    patchify_kernel<<<(N_PATCH_ELEMS / 4 + 255) / 256, 256>>>(images, patch_out);
    vocab_prep_kernel<<<(VROWS * 32 + 255) / 256, 256>>>(vocab);
    gemm_mma_kernel<<<ROWS / M_CTA, 256, SMEM_BYTES>>>(tok_f, tok_i);
    fixup_kernel<<<64, 256>>>(vocab, tok_f, tok_i);
}

// round 6
// speedup vs baseline: 2.9793x; 1.4988x over previous
#include <cuda_runtime.h>
#include <cuda_fp16.h>
#include <cstdint>

// ---------------- problem shapes ----------------
#define B_IMG   64
#define H_IMG   256
#define W_IMG   256
#define PATCH   16
#define ROWS    16384
#define VROWS   4096
#define KDIM    256
#define N_PATCH_ELEMS (ROWS * KDIM)
#define N_TOKENS      ROWS

// ---------------- tiling ----------------
#define M_CTA   128
#define N_TILE  128
#define NT_COUNT (VROWS / N_TILE)          // 32
#define KCHUNK  64
#define NKC     (KDIM / KCHUNK)            // 4
#define NCHUNKS (NT_COUNT * NKC)           // 128
#define TH_GAP  0.05f

// fixup stage A geometry
#define FIX_SLABS   8                       // vocab slabs of 512 rows
#define FIX_VSLAB   (VROWS / FIX_SLABS)     // 512
#define FIX_RPG     4                       // flagged rows per group
#define FIX_GRID    2048                    // FIX_SLABS * 256 groups per sweep
#define FIX_GROUPS  (FIX_GRID / FIX_SLABS)  // 256

// ---------------- SMEM layout (bytes) ----------------
#define SM_A    0
#define SM_B    65536
#define SM_NHV  98304
#define SMEM_BYTES 114688

// ---------------- device scratch ----------------
__device__ float              g_patches[N_PATCH_ELEMS];
__device__ __half             g_ph[N_PATCH_ELEMS];
__device__ __half             g_vh[VROWS * KDIM];
__device__ float              g_nhv2[VROWS];          // -0.5*||v||^2
__device__ int                g_fixcnt;
__device__ int                g_fixlist[ROWS];
__device__ unsigned long long g_keys[ROWS];

// ---------------- helpers ----------------
__device__ __forceinline__ uint32_t smem_u32(const void* p) {
    uint32_t a;
    asm("{ .reg .u64 t; cvta.to.shared.u64 t, %1; cvt.u32.u64 %0, t; }" : "=r"(a) : "l"(p));
    return a;
}
#define SMEM_SWZ(off) ((uint32_t)(off) ^ (((uint32_t)(off) >> 3) & 0x70u))

__device__ __forceinline__ void ldm4(uint32_t* r, uint32_t addr) {
    asm volatile("ldmatrix.sync.aligned.m8n8.x4.shared.b16 {%0,%1,%2,%3}, [%4];"
        : "=r"(r[0]), "=r"(r[1]), "=r"(r[2]), "=r"(r[3]) : "r"(addr));
}
__device__ __forceinline__ void mma_f16(float* c, const uint32_t* a, uint32_t b0, uint32_t b1) {
    asm volatile("mma.sync.aligned.m16n8k16.row.col.f32.f16.f16.f32 "
        "{%0,%1,%2,%3}, {%4,%5,%6,%7}, {%8,%9}, {%0,%1,%2,%3};"
        : "+f"(c[0]), "+f"(c[1]), "+f"(c[2]), "+f"(c[3])
        : "r"(a[0]), "r"(a[1]), "r"(a[2]), "r"(a[3]), "r"(b0), "r"(b1));
}
#define CP16(dst, src)  asm volatile("cp.async.cg.shared.global [%0], [%1], 16;" :: "r"(dst), "l"(src))
#define CP_COMMIT()     asm volatile("cp.async.commit_group;" ::: "memory")
#define CP_WAIT(n)      asm volatile("cp.async.wait_group %0;" :: "n"(n) : "memory")

__device__ __forceinline__ uint32_t pack2h(__half a, __half b) {
    return (uint32_t)__half_as_ushort(a) | ((uint32_t)__half_as_ushort(b) << 16);
}
__device__ __forceinline__ uint32_t ford(float s) {
    uint32_t b = __float_as_uint(s);
    return (b & 0x80000000u) ? ~b : (b | 0x80000000u);
}
__device__ __forceinline__ unsigned long long mkkey(float s, int idx) {
    return ((unsigned long long)ford(s) << 32) | (uint32_t)(~(uint32_t)idx);
}

// ---------------------------------------------------------------------------
// Kernel 1: patchify + fp16 copy
// ---------------------------------------------------------------------------
__global__ void patchify_kernel(const float* __restrict__ img,
                                float* __restrict__ out_opt) {
    int i = blockIdx.x * blockDim.x + threadIdx.x;
    if (blockIdx.x == 0 && threadIdx.x == 0) g_fixcnt = 0;
    if (i >= N_PATCH_ELEMS / 4) return;
    int f  = i << 2;
    int d  = f & 255;
    int pn = f >> 8;
    int b  = pn >> 8;
    int n  = pn & 255;
    int r  = d >> 4, c = d & 15;
    int py = n >> 4, px = n & 15;
    const float4 v = *(const float4*)(img + (size_t)b * (H_IMG * W_IMG)
                                      + (size_t)(py * PATCH + r) * W_IMG + px * PATCH + c);
    ((float4*)g_patches)[i] = v;
    if (out_opt) ((float4*)out_opt)[i] = v;
    uint2 ph;
    ph.x = pack2h(__float2half_rn(v.x), __float2half_rn(v.y));
    ph.y = pack2h(__float2half_rn(v.z), __float2half_rn(v.w));
    ((uint2*)g_ph)[i] = ph;
}

// ---------------------------------------------------------------------------
// Kernel 2: vocab prep — -0.5||v||^2 + fp16 copy (1 warp / row)
// ---------------------------------------------------------------------------
__global__ void vocab_prep_kernel(const float* __restrict__ vocab) {
    int gt   = blockIdx.x * blockDim.x + threadIdx.x;
    int w    = gt >> 5;
    int lane = gt & 31;
    if (w >= VROWS) return;
    float s = 0.f;
    #pragma unroll
    for (int j = 0; j < 2; j++) {
        int e = lane * 4 + j * 128;
        float4 q = *(const float4*)(vocab + (size_t)w * KDIM + e);
        s += q.x * q.x + q.y * q.y + q.z * q.z + q.w * q.w;
        uint2 ph;
        ph.x = pack2h(__float2half_rn(q.x), __float2half_rn(q.y));
        ph.y = pack2h(__float2half_rn(q.z), __float2half_rn(q.w));
        *(uint2*)(g_vh + (size_t)w * KDIM + e) = ph;
    }
    #pragma unroll
    for (int off = 16; off; off >>= 1) s += __shfl_xor_sync(0xFFFFFFFFu, s, off);
    if (lane == 0) g_nhv2[w] = -0.5f * s;
}

// ---------------------------------------------------------------------------
// Kernel 3: single-term fp16 mma.sync GEMM + fused top-2 argmax
// ---------------------------------------------------------------------------
__global__ void __launch_bounds__(256, 1)
gemm_mma_kernel(float* __restrict__ tok_f, int* __restrict__ tok_i) {
    extern __shared__ char smem[];
    const uint32_t sb = smem_u32(smem);
    const int t    = threadIdx.x;
    const int wid  = t >> 5;
    const int lane = t & 31;
    const int wm   = wid >> 2;
    const int wn   = wid & 3;
    const int grp  = lane >> 2;
    const int tig  = lane & 3;
    const int m0   = blockIdx.x * M_CTA;

    for (int i = t; i < VROWS / 4; i += 256)
        ((float4*)(smem + SM_NHV))[i] = ((const float4*)g_nhv2)[i];

    #pragma unroll
    for (int i = 0; i < 16; i++) {
        int f = t + (i << 8);
        int m = f >> 5;
        int c = f & 31;
        int panel = c >> 3;
        int q = c & 7;
        uint32_t dst = SMEM_SWZ(m * 128 + q * 16);
        *(uint4*)(smem + SM_A + panel * 16384 + dst) =
            *(const uint4*)(g_ph + (size_t)(m0 + m) * KDIM + c * 8);
    }
    __syncthreads();

    #pragma unroll
    for (int i = 0; i < 4; i++) {
        int f = t + (i << 8);
        int r = f >> 3, q = f & 7;
        uint32_t dst = sb + SM_B + SMEM_SWZ(r * 128 + q * 16);
        CP16(dst, g_vh + (size_t)r * KDIM + q * 8);
    }
    CP_COMMIT();

    float acc[4][4][4];
    #pragma unroll
    for (int a = 0; a < 4; a++)
        #pragma unroll
        for (int b = 0; b < 4; b++)
            #pragma unroll
            for (int c = 0; c < 4; c++) acc[a][b][c] = 0.f;

    float b1v[8], b2v[8];
    int   i1v[8];
    #pragma unroll
    for (int r = 0; r < 8; r++) { b1v[r] = -3.4e38f; b2v[r] = -3.4e38f; i1v[r] = 0; }

    const float* nhv = (const float*)(smem + SM_NHV);

    for (int gch = 0; gch < NCHUNKS; gch++) {
        const int nt  = gch >> 2;
        const int kc  = gch & 3;
        const int buf = gch & 1;

        if (gch < NCHUNKS - 1) {
            const int gn  = gch + 1;
            const int nn0 = (gn >> 2) << 7;
            const int nkc = gn & 3;
            const uint32_t bb = sb + SM_B + (gn & 1) * 16384;
            #pragma unroll
            for (int i = 0; i < 4; i++) {
                int f = t + (i << 8);
                int r = f >> 3, q = f & 7;
                uint32_t dst = bb + SMEM_SWZ(r * 128 + q * 16);
                CP16(dst, g_vh + (size_t)(nn0 + r) * KDIM + nkc * 64 + q * 8);
            }
            CP_COMMIT();
            CP_WAIT(1);
        } else {
            CP_WAIT(0);
        }
        __syncthreads();

        const uint32_t b_base = sb + SM_B + buf * 16384;
        const uint32_t a_base = sb + SM_A + kc * 16384;
        const int rowA = wm * 64 + (lane & 15);
        const int rowB = wn * 32 + (lane & 15);

        #pragma unroll
        for (int ks = 0; ks < 4; ks++) {
            const uint32_t colb = ks * 32 + (lane >> 4) * 16;
            uint32_t ah[4][4], bh[2][4];
            #pragma unroll
            for (int mt = 0; mt < 4; mt++)
                ldm4(ah[mt], a_base + SMEM_SWZ((rowA + mt * 16) * 128 + colb));
            #pragma unroll
            for (int p = 0; p < 2; p++)
                ldm4(bh[p], b_base + SMEM_SWZ((rowB + p * 16) * 128 + colb));
            #pragma unroll
            for (int mt = 0; mt < 4; mt++) {
                #pragma unroll
                for (int n8 = 0; n8 < 4; n8++) {
                    const int p = n8 >> 1, w = n8 & 1;
                    mma_f16(acc[mt][n8], ah[mt],
                            w ? bh[p][1] : bh[p][0],
                            w ? bh[p][3] : bh[p][2]);
                }
            }
        }
        __syncthreads();

        if (kc == 3) {
            #pragma unroll
            for (int mt = 0; mt < 4; mt++) {
                #pragma unroll
                for (int n8 = 0; n8 < 4; n8++) {
                    const int cb = nt * 128 + wn * 32 + n8 * 8 + tig * 2;
                    const float2 h = *(const float2*)(nhv + cb);
                    const float s00 = acc[mt][n8][0] + h.x;
                    const float s01 = acc[mt][n8][1] + h.y;
                    const float s10 = acc[mt][n8][2] + h.x;
                    const float s11 = acc[mt][n8][3] + h.y;
                    const int r0 = mt * 2, r1 = mt * 2 + 1;
                    if (s00 > b1v[r0]) { b2v[r0] = b1v[r0]; b1v[r0] = s00; i1v[r0] = cb; }
                    else if (s00 > b2v[r0]) b2v[r0] = s00;
                    if (s01 > b1v[r0]) { b2v[r0] = b1v[r0]; b1v[r0] = s01; i1v[r0] = cb + 1; }
                    else if (s01 > b2v[r0]) b2v[r0] = s01;
                    if (s10 > b1v[r1]) { b2v[r1] = b1v[r1]; b1v[r1] = s10; i1v[r1] = cb; }
                    else if (s10 > b2v[r1]) b2v[r1] = s10;
                    if (s11 > b1v[r1]) { b2v[r1] = b1v[r1]; b1v[r1] = s11; i1v[r1] = cb + 1; }
                    else if (s11 > b2v[r1]) b2v[r1] = s11;
                    acc[mt][n8][0] = 0.f; acc[mt][n8][1] = 0.f;
                    acc[mt][n8][2] = 0.f; acc[mt][n8][3] = 0.f;
                }
            }
        }
    }

    #pragma unroll
    for (int d = 1; d <= 2; d <<= 1) {
        #pragma unroll
        for (int r = 0; r < 8; r++) {
            float ob1 = __shfl_xor_sync(0xFFFFFFFFu, b1v[r], d);
            float ob2 = __shfl_xor_sync(0xFFFFFFFFu, b2v[r], d);
            int   oi1 = __shfl_xor_sync(0xFFFFFFFFu, i1v[r], d);
            if (ob1 > b1v[r] || (ob1 == b1v[r] && oi1 < i1v[r])) {
                b2v[r] = fmaxf(b1v[r], ob2);
                b1v[r] = ob1; i1v[r] = oi1;
            } else {
                b2v[r] = fmaxf(b2v[r], ob1);
            }
        }
    }

    __syncthreads();
    float4* red = (float4*)(smem + SM_B);
    if (tig == 0) {
        #pragma unroll
        for (int mt = 0; mt < 4; mt++) {
            #pragma unroll
            for (int h = 0; h < 2; h++) {
                const int rl = wm * 64 + mt * 16 + grp + h * 8;
                const int r  = mt * 2 + h;
                red[wn * 128 + rl] = make_float4(b1v[r], b2v[r], __int_as_float(i1v[r]), 0.f);
            }
        }
    }
    __syncthreads();
    if (t < M_CTA) {
        float bb1 = -3.4e38f, bb2 = -3.4e38f;
        int   bi  = 0x7FFFFFFF;
        #pragma unroll
        for (int w = 0; w < 4; w++) {
            float4 e = red[w * 128 + t];
            float ob1 = e.x, ob2 = e.y;
            int   oi1 = __float_as_int(e.z);
            if (ob1 > bb1 || (ob1 == bb1 && oi1 < bi)) {
                bb2 = fmaxf(bb1, ob2); bb1 = ob1; bi = oi1;
            } else {
                bb2 = fmaxf(bb2, ob1);
            }
        }
        const int row = m0 + t;
        if (tok_f) tok_f[row] = (float)bi;
        if (tok_i) tok_i[row] = bi;
        if (bb1 - bb2 < TH_GAP) {
            int pos = atomicAdd(&g_fixcnt, 1);
            g_fixlist[pos] = row;
            g_keys[pos]    = 0ULL;
        }
    }
}

// ---------------------------------------------------------------------------
// Kernel 4a: exact fp32 rescore, parallel over (row-group, vocab-slab).
//   2048 blocks; block = 4 flagged rows x 512 vocab rows. atomicMax merge.
// ---------------------------------------------------------------------------
__global__ void __launch_bounds__(256)
fixup_score_kernel(const float* __restrict__ vocab) {
    __shared__ float xs[FIX_RPG][KDIM];
    __shared__ float rbv[FIX_RPG][256];
    __shared__ int   rbi[FIX_RPG][256];
    const int t    = threadIdx.x;
    const int cnt  = g_fixcnt;
    const int slab = blockIdx.x & (FIX_SLABS - 1);
    const int v0   = slab * FIX_VSLAB;

    for (int rg = blockIdx.x >> 3; rg * FIX_RPG < cnt; rg += FIX_GROUPS) {
        const int base = rg * FIX_RPG;
        const int nr   = min(FIX_RPG, cnt - base);
        __syncthreads();
        for (int i = t; i < nr * KDIM; i += 256) {
            int r = i >> 8, k = i & 255;
            xs[r][k] = g_patches[(size_t)g_fixlist[base + r] * KDIM + k];
        }
        __syncthreads();

        float best[FIX_RPG];
        int   bidx[FIX_RPG];
        #pragma unroll
        for (int r = 0; r < FIX_RPG; r++) { best[r] = -3.4e38f; bidx[r] = 0; }

        #pragma unroll
        for (int j = 0; j < FIX_VSLAB / 256; j++) {
            const int v = v0 + t + j * 256;
            const float4* vr = (const float4*)(vocab + (size_t)v * KDIM);
            float acc[FIX_RPG];
            #pragma unroll
            for (int r = 0; r < FIX_RPG; r++) acc[r] = 0.f;
            #pragma unroll 8
            for (int k = 0; k < KDIM / 4; k++) {
                float4 q = vr[k];
                #pragma unroll
                for (int r = 0; r < FIX_RPG; r++) {
                    const float4 x = *(const float4*)&xs[r][4 * k];
                    acc[r] = fmaf(x.x, q.x, acc[r]);
                    acc[r] = fmaf(x.y, q.y, acc[r]);
                    acc[r] = fmaf(x.z, q.z, acc[r]);
                    acc[r] = fmaf(x.w, q.w, acc[r]);
                }
            }
            const float h = g_nhv2[v];
            #pragma unroll
            for (int r = 0; r < FIX_RPG; r++) {
                float s = acc[r] + h;
                if (s > best[r] || (s == best[r] && v < bidx[r])) { best[r] = s; bidx[r] = v; }
            }
        }
        #pragma unroll
        for (int r = 0; r < FIX_RPG; r++) { rbv[r][t] = best[r]; rbi[r][t] = bidx[r]; }
        __syncthreads();

        const int w = t >> 5, lane = t & 31;
        if (w < nr) {
            float bs = -3.4e38f;
            int   bj = 0x7FFFFFFF;
            #pragma unroll
            for (int j = 0; j < 8; j++) {
                float s  = rbv[w][lane + 32 * j];
                int   id = rbi[w][lane + 32 * j];
                if (s > bs || (s == bs && id < bj)) { bs = s; bj = id; }
            }
            #pragma unroll
            for (int off = 16; off; off >>= 1) {
                float os  = __shfl_xor_sync(0xFFFFFFFFu, bs, off);
                int   oid = __shfl_xor_sync(0xFFFFFFFFu, bj, off);
                if (os > bs || (os == bs && oid < bj)) { bs = os; bj = oid; }
            }
            if (lane == 0) atomicMax(&g_keys[base + w], mkkey(bs, bj));
        }
    }
}

// ---------------------------------------------------------------------------
// Kernel 4b: decode keys -> tokens for flagged rows
// ---------------------------------------------------------------------------
__global__ void __launch_bounds__(256)
fixup_write_kernel(float* __restrict__ tok_f, int* __restrict__ tok_i) {
    const int i = blockIdx.x * blockDim.x + threadIdx.x;
    if (i >= g_fixcnt) return;
    const int row = g_fixlist[i];
    const int idx = (int)(~(uint32_t)(g_keys[i] & 0xFFFFFFFFull));
    if (tok_f) tok_f[row] = (float)idx;
    if (tok_i) tok_i[row] = idx;
}

// ---------------------------------------------------------------------------
extern "C" void kernel_launch(void* const* d_in, const int* in_sizes, int n_in,
                              void* d_out, int out_size) {
    const float* images = (const float*)d_in[0];
    const float* vocab  = (const float*)d_in[1];

    float* out       = (float*)d_out;
    float* patch_out = nullptr;
    float* tok_f     = nullptr;
    int*   tok_i     = nullptr;
    if (out_size >= N_PATCH_ELEMS + N_TOKENS) {
        patch_out = out;
        tok_f     = out + N_PATCH_ELEMS;
    } else if (out_size == N_PATCH_ELEMS) {
        patch_out = out;
    } else {
        tok_i = (int*)d_out;
    }

    cudaFuncSetAttribute(gemm_mma_kernel,
                         cudaFuncAttributeMaxDynamicSharedMemorySize, SMEM_BYTES);

    patchify_kernel<<<(N_PATCH_ELEMS / 4 + 255) / 256, 256>>>(images, patch_out);
    vocab_prep_kernel<<<(VROWS * 32 + 255) / 256, 256>>>(vocab);
    gemm_mma_kernel<<<ROWS / M_CTA, 256, SMEM_BYTES>>>(tok_f, tok_i);
    fixup_score_kernel<<<FIX_GRID, 256>>>(vocab);
    fixup_write_kernel<<<ROWS / 256, 256>>>(tok_f, tok_i);
}